// round 15
// baseline (speedup 1.0000x reference)
#include <cuda_runtime.h>
#include <cstddef>

// Problem constants (fixed by the reference):
//   B_PAIRS=2048 pairs, each pair = 44 ligand nodes + 300 protein nodes (stride 344)
//   Only the ligand segment sums (even segments) feed the MLP.
//   MLP: 128 ->256 relu -> 128 relu -> 64 relu -> 1
#define B_PAIRS 2048
#define LIG     44
#define STRIDE  344
#define F_IN    128
#define N0      256
#define N1      128
#define N2      64
#define RTILE   8
#define THREADS 256
#define NMLP    (B_PAIRS / RTILE)        // 256 consumer blocks
#define GRID    (B_PAIRS + NMLP)         // 2304 total

typedef unsigned long long u64;

// Scratch: per-pair feature sums + per-consumer ready counters.
__device__ float g_xs[B_PAIRS * F_IN];
__device__ int   g_cnt[NMLP];            // zero at load; consumers self-reset

// ---------------- packed fp32x2 helpers (sm_103a FFMA2) --------------------
#define PACK_F32X2(d, lo, hi) \
    asm("mov.b64 %0, {%1, %2};" : "=l"(d) : "f"(lo), "f"(hi))
#define UNPACK_F32X2(lo, hi, v) \
    asm("mov.b64 {%0, %1}, %2;" : "=f"(lo), "=f"(hi) : "l"(v))
#define FMA_F32X2(d, a, b, c) \
    asm("fma.rn.f32x2 %0, %1, %2, %3;" : "=l"(d) : "l"(a), "l"(b), "l"(c))
#define ADD_F32X2(d, a, b) \
    asm("add.rn.f32x2 %0, %1, %2;" : "=l"(d) : "l"(a), "l"(b))

// ============================================================================
// Fused kernel. Blocks [0, 2048): segment-sum producers (one pair each).
// Blocks [2048, 2304): MLP consumers (8 pairs each), spin on g_cnt.
// Producers never wait; dispatch order is bid-increasing -> deadlock-free.
// Consumers reset their counter after reading -> replay-deterministic.
// ============================================================================
__global__ void __launch_bounds__(THREADS)
fused_fcnn(const float* __restrict__ features,
           const float* __restrict__ W0, const float* __restrict__ b0,
           const float* __restrict__ W1, const float* __restrict__ b1,
           const float* __restrict__ W2, const float* __restrict__ b2,
           const float* __restrict__ Wout, const float* __restrict__ bout,
           float* __restrict__ out)
{
    __shared__ __align__(16) u64  xsP[F_IN][RTILE / 2];  // 4 KB raw row-pairs
    __shared__ __align__(16) u64  h0P[N0][RTILE / 2];    // 8 KB
    __shared__ __align__(16) u64  h1P[N1][RTILE / 2];    // 4 KB
    __shared__ __align__(16) float h2T[N2][RTILE];       // 2 KB
    __shared__ __align__(16) u64  pbuf[7 * 32 * 8];      // 14 KB (also seg scratch)

    const int tid = threadIdx.x;

    // ======================= Producer role =================================
    if (blockIdx.x < B_PAIRS) {
        const int pair = blockIdx.x;
        const int c4   = tid & 31;
        const int g    = tid >> 5;

        float4* part = reinterpret_cast<float4*>(pbuf);  // [8][32]
        const float4* src = reinterpret_cast<const float4*>(features)
                          + (size_t)pair * STRIDE * (F_IN / 4) + c4;
        float4 acc = make_float4(0.f, 0.f, 0.f, 0.f);
#pragma unroll
        for (int r = g; r < LIG; r += 8) {
            float4 v = src[(size_t)r * (F_IN / 4)];
            acc.x += v.x; acc.y += v.y; acc.z += v.z; acc.w += v.w;
        }
        part[g * 32 + c4] = acc;
        __syncthreads();

        if (tid < 32) {
            float4 s = part[tid];
#pragma unroll
            for (int gg = 1; gg < 8; ++gg) {
                float4 v = part[gg * 32 + tid];
                s.x += v.x; s.y += v.y; s.z += v.z; s.w += v.w;
            }
            reinterpret_cast<float4*>(g_xs)[pair * (F_IN / 4) + tid] = s;
        }
        __syncthreads();
        if (tid == 0) {
            __threadfence();
            atomicAdd(&g_cnt[pair >> 3], 1);
        }
        return;
    }

    // ======================= Consumer role =================================
    const int b  = blockIdx.x - B_PAIRS;
    const int p0 = b * RTILE;

    if (tid == 0) {
        volatile int* cp = &g_cnt[b];
        while (*cp < RTILE) { }
        __threadfence();
    }
    __syncthreads();

    // Load 8 summed rows. Raw layout: xsP[k][rp] viewed as float[k][8].
    {
        const int pp = tid & 7;
        const int c4 = tid >> 3;                 // 0..31
        float4 v = reinterpret_cast<const float4*>(g_xs)
                       [(size_t)(p0 + pp) * (F_IN / 4) + c4];
        float* xf = reinterpret_cast<float*>(&xsP[0][0]);
        xf[(c4 * 4 + 0) * RTILE + pp] = v.x;
        xf[(c4 * 4 + 1) * RTILE + pp] = v.y;
        xf[(c4 * 4 + 2) * RTILE + pp] = v.z;
        xf[(c4 * 4 + 3) * RTILE + pp] = v.w;
    }
    __syncthreads();
    if (tid == 0) g_cnt[b] = 0;                  // self-reset for next replay

    // ======== Layer 0: [8,128]@[128,256]+b relu | 128 cp x 2 kq x 64 ========
    {
        const int ct = tid & 127;                // colpair: cols 2ct, 2ct+1
        const int kq = tid >> 7;                 // 0/1, 64 k each
        u64 acc[8];
#pragma unroll
        for (int i = 0; i < 8; ++i) acc[i] = 0ull;
        const float* Wp = W0 + (size_t)(kq * 64) * N0 + 2 * ct;
#pragma unroll 8
        for (int kk = 0; kk < 64; ++kk) {
            float2 wv = *reinterpret_cast<const float2*>(Wp + (size_t)kk * N0);
            u64 wd0, wd1;
            PACK_F32X2(wd0, wv.x, wv.x);
            PACK_F32X2(wd1, wv.y, wv.y);
            const u64* ap = &xsP[kq * 64 + kk][0];
            ulonglong2 a01 = *reinterpret_cast<const ulonglong2*>(ap);
            ulonglong2 a23 = *reinterpret_cast<const ulonglong2*>(ap + 2);
            FMA_F32X2(acc[0], a01.x, wd0, acc[0]);
            FMA_F32X2(acc[1], a01.y, wd0, acc[1]);
            FMA_F32X2(acc[2], a23.x, wd0, acc[2]);
            FMA_F32X2(acc[3], a23.y, wd0, acc[3]);
            FMA_F32X2(acc[4], a01.x, wd1, acc[4]);
            FMA_F32X2(acc[5], a01.y, wd1, acc[5]);
            FMA_F32X2(acc[6], a23.x, wd1, acc[6]);
            FMA_F32X2(acc[7], a23.y, wd1, acc[7]);
        }
        if (kq == 1) {
            u64* dst = &pbuf[ct * 8];
#pragma unroll
            for (int i = 0; i < 8; i += 2)
                *reinterpret_cast<ulonglong2*>(dst + i) =
                    make_ulonglong2(acc[i], acc[i + 1]);
        }
        __syncthreads();
        if (kq == 0) {
            const u64* q = &pbuf[ct * 8];
#pragma unroll
            for (int i = 0; i < 8; i += 2) {
                ulonglong2 qq = *reinterpret_cast<const ulonglong2*>(q + i);
                ADD_F32X2(acc[i],     acc[i],     qq.x);
                ADD_F32X2(acc[i + 1], acc[i + 1], qq.y);
            }
            float2 bv = *reinterpret_cast<const float2*>(b0 + 2 * ct);
            u64 bb0, bb1;
            PACK_F32X2(bb0, bv.x, bv.x);
            PACK_F32X2(bb1, bv.y, bv.y);
#pragma unroll
            for (int i = 0; i < 8; ++i) {
                ADD_F32X2(acc[i], acc[i], (i < 4) ? bb0 : bb1);
                float v0, v1; UNPACK_F32X2(v0, v1, acc[i]);
                PACK_F32X2(acc[i], fmaxf(v0, 0.f), fmaxf(v1, 0.f));
            }
            *reinterpret_cast<ulonglong2*>(&h0P[2 * ct][0]) =
                make_ulonglong2(acc[0], acc[1]);
            *reinterpret_cast<ulonglong2*>(&h0P[2 * ct][2]) =
                make_ulonglong2(acc[2], acc[3]);
            *reinterpret_cast<ulonglong2*>(&h0P[2 * ct + 1][0]) =
                make_ulonglong2(acc[4], acc[5]);
            *reinterpret_cast<ulonglong2*>(&h0P[2 * ct + 1][2]) =
                make_ulonglong2(acc[6], acc[7]);
        }
    }
    __syncthreads();

    // ======== Layer 1: [8,256]@[256,128]+b relu | 64 cp x 4 kq x 64 =========
    {
        const int ct = tid & 63;
        const int kq = tid >> 6;                 // 0..3, 64 k each
        u64 acc[8];
#pragma unroll
        for (int i = 0; i < 8; ++i) acc[i] = 0ull;
        const float* Wp = W1 + (size_t)(kq * 64) * N1 + 2 * ct;
#pragma unroll 8
        for (int kk = 0; kk < 64; ++kk) {
            float2 wv = *reinterpret_cast<const float2*>(Wp + (size_t)kk * N1);
            u64 wd0, wd1;
            PACK_F32X2(wd0, wv.x, wv.x);
            PACK_F32X2(wd1, wv.y, wv.y);
            const u64* ap = &h0P[kq * 64 + kk][0];
            ulonglong2 a01 = *reinterpret_cast<const ulonglong2*>(ap);
            ulonglong2 a23 = *reinterpret_cast<const ulonglong2*>(ap + 2);
            FMA_F32X2(acc[0], a01.x, wd0, acc[0]);
            FMA_F32X2(acc[1], a01.y, wd0, acc[1]);
            FMA_F32X2(acc[2], a23.x, wd0, acc[2]);
            FMA_F32X2(acc[3], a23.y, wd0, acc[3]);
            FMA_F32X2(acc[4], a01.x, wd1, acc[4]);
            FMA_F32X2(acc[5], a01.y, wd1, acc[5]);
            FMA_F32X2(acc[6], a23.x, wd1, acc[6]);
            FMA_F32X2(acc[7], a23.y, wd1, acc[7]);
        }
        if (kq > 0) {
            u64* dst = &pbuf[((kq - 1) * 64 + ct) * 8];
#pragma unroll
            for (int i = 0; i < 8; i += 2)
                *reinterpret_cast<ulonglong2*>(dst + i) =
                    make_ulonglong2(acc[i], acc[i + 1]);
        }
        __syncthreads();
        if (kq == 0) {
#pragma unroll
            for (int t = 0; t < 3; ++t) {
                const u64* q = &pbuf[(t * 64 + ct) * 8];
#pragma unroll
                for (int i = 0; i < 8; i += 2) {
                    ulonglong2 qq = *reinterpret_cast<const ulonglong2*>(q + i);
                    ADD_F32X2(acc[i],     acc[i],     qq.x);
                    ADD_F32X2(acc[i + 1], acc[i + 1], qq.y);
                }
            }
            float2 bv = *reinterpret_cast<const float2*>(b1 + 2 * ct);
            u64 bb0, bb1;
            PACK_F32X2(bb0, bv.x, bv.x);
            PACK_F32X2(bb1, bv.y, bv.y);
#pragma unroll
            for (int i = 0; i < 8; ++i) {
                ADD_F32X2(acc[i], acc[i], (i < 4) ? bb0 : bb1);
                float v0, v1; UNPACK_F32X2(v0, v1, acc[i]);
                PACK_F32X2(acc[i], fmaxf(v0, 0.f), fmaxf(v1, 0.f));
            }
            *reinterpret_cast<ulonglong2*>(&h1P[2 * ct][0]) =
                make_ulonglong2(acc[0], acc[1]);
            *reinterpret_cast<ulonglong2*>(&h1P[2 * ct][2]) =
                make_ulonglong2(acc[2], acc[3]);
            *reinterpret_cast<ulonglong2*>(&h1P[2 * ct + 1][0]) =
                make_ulonglong2(acc[4], acc[5]);
            *reinterpret_cast<ulonglong2*>(&h1P[2 * ct + 1][2]) =
                make_ulonglong2(acc[6], acc[7]);
        }
    }
    __syncthreads();

    // ======== Layer 2: [8,128]@[128,64]+b relu | 32 cp x 8 kq x 16 ==========
    {
        const int ct = tid & 31;
        const int kq = tid >> 5;                 // 0..7, 16 k each
        u64 acc[8];
#pragma unroll
        for (int i = 0; i < 8; ++i) acc[i] = 0ull;
        const float* Wp = W2 + (size_t)(kq * 16) * N2 + 2 * ct;
#pragma unroll
        for (int kk = 0; kk < 16; ++kk) {
            float2 wv = *reinterpret_cast<const float2*>(Wp + (size_t)kk * N2);
            u64 wd0, wd1;
            PACK_F32X2(wd0, wv.x, wv.x);
            PACK_F32X2(wd1, wv.y, wv.y);
            const u64* ap = &h1P[kq * 16 + kk][0];
            ulonglong2 a01 = *reinterpret_cast<const ulonglong2*>(ap);
            ulonglong2 a23 = *reinterpret_cast<const ulonglong2*>(ap + 2);
            FMA_F32X2(acc[0], a01.x, wd0, acc[0]);
            FMA_F32X2(acc[1], a01.y, wd0, acc[1]);
            FMA_F32X2(acc[2], a23.x, wd0, acc[2]);
            FMA_F32X2(acc[3], a23.y, wd0, acc[3]);
            FMA_F32X2(acc[4], a01.x, wd1, acc[4]);
            FMA_F32X2(acc[5], a01.y, wd1, acc[5]);
            FMA_F32X2(acc[6], a23.x, wd1, acc[6]);
            FMA_F32X2(acc[7], a23.y, wd1, acc[7]);
        }
        if (kq > 0) {
            u64* dst = &pbuf[((kq - 1) * 32 + ct) * 8];
#pragma unroll
            for (int i = 0; i < 8; i += 2)
                *reinterpret_cast<ulonglong2*>(dst + i) =
                    make_ulonglong2(acc[i], acc[i + 1]);
        }
        __syncthreads();
        if (kq == 0) {
#pragma unroll
            for (int t = 0; t < 7; ++t) {
                const u64* q = &pbuf[(t * 32 + ct) * 8];
#pragma unroll
                for (int i = 0; i < 8; i += 2) {
                    ulonglong2 qq = *reinterpret_cast<const ulonglong2*>(q + i);
                    ADD_F32X2(acc[i],     acc[i],     qq.x);
                    ADD_F32X2(acc[i + 1], acc[i + 1], qq.y);
                }
            }
            float2 bv = *reinterpret_cast<const float2*>(b2 + 2 * ct);
            u64 bb0, bb1;
            PACK_F32X2(bb0, bv.x, bv.x);
            PACK_F32X2(bb1, bv.y, bv.y);
#pragma unroll
            for (int i = 0; i < 8; ++i) {
                ADD_F32X2(acc[i], acc[i], (i < 4) ? bb0 : bb1);
                float v0, v1; UNPACK_F32X2(v0, v1, acc[i]);
                const int c  = 2 * ct + (i >> 2);
                const int rp = i & 3;
                h2T[c][2 * rp    ] = fmaxf(v0, 0.f);
                h2T[c][2 * rp + 1] = fmaxf(v1, 0.f);
            }
        }
    }
    __syncthreads();

    // ======== Output: [8,64]@[64,1]+b  (8 warps = 8 rows) ===================
    {
        const int warp = tid >> 5;
        const int lane = tid & 31;
        float s = h2T[2 * lane][warp]     * Wout[2 * lane]
                + h2T[2 * lane + 1][warp] * Wout[2 * lane + 1];
#pragma unroll
        for (int o = 16; o > 0; o >>= 1)
            s += __shfl_down_sync(0xffffffffu, s, o);
        if (lane == 0)
            out[p0 + warp] = s + bout[0];
    }
}

// d_in order (metadata): [0] batch_num_nodes (unused), [1] features,
// [2] W0, [3] b0, [4] W1, [5] b1, [6] W2, [7] b2, [8] Wout, [9] bout.
extern "C" void kernel_launch(void* const* d_in, const int* in_sizes, int n_in,
                              void* d_out, int out_size)
{
    const float* features = (const float*)d_in[1];
    const float* W0   = (const float*)d_in[2];
    const float* b0   = (const float*)d_in[3];
    const float* W1   = (const float*)d_in[4];
    const float* b1   = (const float*)d_in[5];
    const float* W2   = (const float*)d_in[6];
    const float* b2   = (const float*)d_in[7];
    const float* Wout = (const float*)d_in[8];
    const float* bout = (const float*)d_in[9];
    float* out = (float*)d_out;

    fused_fcnn<<<GRID, THREADS>>>(features, W0, b0, W1, b1, W2, b2,
                                  Wout, bout, out);
}

// round 16
// speedup vs baseline: 1.5854x; 1.5854x over previous
#include <cuda_runtime.h>
#include <cstddef>

// Problem constants (fixed by the reference):
//   B_PAIRS=2048 pairs, each pair = 44 ligand nodes + 300 protein nodes (stride 344)
//   Only the ligand segment sums (even segments) feed the MLP.
//   MLP: 128 ->256 relu -> 128 relu -> 64 relu -> 1
#define B_PAIRS 2048
#define LIG     44
#define STRIDE  344
#define F_IN    128
#define N0      256
#define N1      128
#define N2      64
#define RTILE   8          // pairs per MLP block -> grid 256
#define THREADS 256

typedef unsigned long long u64;

// 1 MB scratch for the per-pair feature sums.
__device__ float g_xs[B_PAIRS * F_IN];

// ---------------- packed fp32x2 helpers (sm_103a FFMA2) --------------------
#define PACK_F32X2(d, lo, hi) \
    asm("mov.b64 %0, {%1, %2};" : "=l"(d) : "f"(lo), "f"(hi))
#define UNPACK_F32X2(lo, hi, v) \
    asm("mov.b64 {%0, %1}, %2;" : "=f"(lo), "=f"(hi) : "l"(v))
#define FMA_F32X2(d, a, b, c) \
    asm("fma.rn.f32x2 %0, %1, %2, %3;" : "=l"(d) : "l"(a), "l"(b), "l"(c))
#define ADD_F32X2(d, a, b) \
    asm("add.rn.f32x2 %0, %1, %2;" : "=l"(d) : "l"(a), "l"(b))

// ============================================================================
// Kernel A: ligand segment sum. One block per pair. Default caching so the
// 46 MB ligand hot-set stays L2-resident across graph replays.
// ============================================================================
__global__ void __launch_bounds__(THREADS)
seg_sum_kernel(const float* __restrict__ features)
{
    __shared__ float4 part[8][32];
    const int tid  = threadIdx.x;
    const int pair = blockIdx.x;
    const int c4   = tid & 31;
    const int g    = tid >> 5;

    const float4* src = reinterpret_cast<const float4*>(features)
                      + (size_t)pair * STRIDE * (F_IN / 4) + c4;
    float4 acc = make_float4(0.f, 0.f, 0.f, 0.f);
#pragma unroll
    for (int r = g; r < LIG; r += 8) {
        float4 v = src[(size_t)r * (F_IN / 4)];
        acc.x += v.x; acc.y += v.y; acc.z += v.z; acc.w += v.w;
    }
    part[g][c4] = acc;
    __syncthreads();

    if (tid < 32) {
        float4 s = part[0][tid];
#pragma unroll
        for (int gg = 1; gg < 8; ++gg) {
            float4 v = part[gg][tid];
            s.x += v.x; s.y += v.y; s.z += v.z; s.w += v.w;
        }
        reinterpret_cast<float4*>(g_xs)[pair * (F_IN / 4) + tid] = s;
    }
}

// ============================================================================
// Kernel B (R11 + weight prefetch): 4-layer MLP, RTILE=8, grid=256, 256 thr.
// Activations raw row-pairs; weights LDG.64 with a DEPTH-4 register ring so
// each load is issued ~4 iterations before use (covers L2-hit latency; L1D
// is flushed per launch so weights always come from L2 on replay).
// ============================================================================
__global__ void __launch_bounds__(THREADS)
mlp_kernel(const float* __restrict__ W0, const float* __restrict__ b0,
           const float* __restrict__ W1, const float* __restrict__ b1,
           const float* __restrict__ W2, const float* __restrict__ b2,
           const float* __restrict__ Wout, const float* __restrict__ bout,
           float* __restrict__ out)
{
    __shared__ __align__(16) u64  xsP[F_IN][RTILE / 2];  // 4 KB raw row-pairs
    __shared__ __align__(16) u64  h0P[N0][RTILE / 2];    // 8 KB
    __shared__ __align__(16) u64  h1P[N1][RTILE / 2];    // 4 KB
    __shared__ __align__(16) float h2T[N2][RTILE];       // 2 KB
    __shared__ __align__(16) u64  pbuf[7 * 32 * 8];      // 14 KB partials

    const int tid = threadIdx.x;
    const int p0  = blockIdx.x * RTILE;

    // Load 8 summed rows. Raw layout: xsP[k][rp] viewed as float[k][8].
    {
        const int pp = tid & 7;
        const int c4 = tid >> 3;                 // 0..31
        float4 v = reinterpret_cast<const float4*>(g_xs)
                       [(size_t)(p0 + pp) * (F_IN / 4) + c4];
        float* xf = reinterpret_cast<float*>(&xsP[0][0]);
        xf[(c4 * 4 + 0) * RTILE + pp] = v.x;
        xf[(c4 * 4 + 1) * RTILE + pp] = v.y;
        xf[(c4 * 4 + 2) * RTILE + pp] = v.z;
        xf[(c4 * 4 + 3) * RTILE + pp] = v.w;
    }
    __syncthreads();

    // ======== Layer 0: [8,128]@[128,256]+b relu | 128 cp x 2 kq x 64 ========
    {
        const int ct = tid & 127;                // colpair: cols 2ct, 2ct+1
        const int kq = tid >> 7;                 // 0/1, 64 k each
        u64 acc[8];
#pragma unroll
        for (int i = 0; i < 8; ++i) acc[i] = 0ull;
        const float* Wp = W0 + (size_t)(kq * 64) * N0 + 2 * ct;

        float2 wr[4];
#pragma unroll
        for (int i = 0; i < 4; ++i)
            wr[i] = *reinterpret_cast<const float2*>(Wp + (size_t)i * N0);

#pragma unroll 8
        for (int kk = 0; kk < 64; ++kk) {
            float2 wv = wr[kk & 3];
            if (kk + 4 < 64)
                wr[kk & 3] = *reinterpret_cast<const float2*>(
                                 Wp + (size_t)(kk + 4) * N0);
            u64 wd0, wd1;
            PACK_F32X2(wd0, wv.x, wv.x);
            PACK_F32X2(wd1, wv.y, wv.y);
            const u64* ap = &xsP[kq * 64 + kk][0];
            ulonglong2 a01 = *reinterpret_cast<const ulonglong2*>(ap);
            ulonglong2 a23 = *reinterpret_cast<const ulonglong2*>(ap + 2);
            FMA_F32X2(acc[0], a01.x, wd0, acc[0]);
            FMA_F32X2(acc[1], a01.y, wd0, acc[1]);
            FMA_F32X2(acc[2], a23.x, wd0, acc[2]);
            FMA_F32X2(acc[3], a23.y, wd0, acc[3]);
            FMA_F32X2(acc[4], a01.x, wd1, acc[4]);
            FMA_F32X2(acc[5], a01.y, wd1, acc[5]);
            FMA_F32X2(acc[6], a23.x, wd1, acc[6]);
            FMA_F32X2(acc[7], a23.y, wd1, acc[7]);
        }
        if (kq == 1) {
            u64* dst = &pbuf[ct * 8];
#pragma unroll
            for (int i = 0; i < 8; i += 2)
                *reinterpret_cast<ulonglong2*>(dst + i) =
                    make_ulonglong2(acc[i], acc[i + 1]);
        }
        __syncthreads();
        if (kq == 0) {
            const u64* q = &pbuf[ct * 8];
#pragma unroll
            for (int i = 0; i < 8; i += 2) {
                ulonglong2 qq = *reinterpret_cast<const ulonglong2*>(q + i);
                ADD_F32X2(acc[i],     acc[i],     qq.x);
                ADD_F32X2(acc[i + 1], acc[i + 1], qq.y);
            }
            float2 bv = *reinterpret_cast<const float2*>(b0 + 2 * ct);
            u64 bb0, bb1;
            PACK_F32X2(bb0, bv.x, bv.x);
            PACK_F32X2(bb1, bv.y, bv.y);
#pragma unroll
            for (int i = 0; i < 8; ++i) {
                ADD_F32X2(acc[i], acc[i], (i < 4) ? bb0 : bb1);
                float v0, v1; UNPACK_F32X2(v0, v1, acc[i]);
                PACK_F32X2(acc[i], fmaxf(v0, 0.f), fmaxf(v1, 0.f));
            }
            *reinterpret_cast<ulonglong2*>(&h0P[2 * ct][0]) =
                make_ulonglong2(acc[0], acc[1]);
            *reinterpret_cast<ulonglong2*>(&h0P[2 * ct][2]) =
                make_ulonglong2(acc[2], acc[3]);
            *reinterpret_cast<ulonglong2*>(&h0P[2 * ct + 1][0]) =
                make_ulonglong2(acc[4], acc[5]);
            *reinterpret_cast<ulonglong2*>(&h0P[2 * ct + 1][2]) =
                make_ulonglong2(acc[6], acc[7]);
        }
    }
    __syncthreads();

    // ======== Layer 1: [8,256]@[256,128]+b relu | 64 cp x 4 kq x 64 =========
    {
        const int ct = tid & 63;
        const int kq = tid >> 6;                 // 0..3, 64 k each
        u64 acc[8];
#pragma unroll
        for (int i = 0; i < 8; ++i) acc[i] = 0ull;
        const float* Wp = W1 + (size_t)(kq * 64) * N1 + 2 * ct;

        float2 wr[4];
#pragma unroll
        for (int i = 0; i < 4; ++i)
            wr[i] = *reinterpret_cast<const float2*>(Wp + (size_t)i * N1);

#pragma unroll 8
        for (int kk = 0; kk < 64; ++kk) {
            float2 wv = wr[kk & 3];
            if (kk + 4 < 64)
                wr[kk & 3] = *reinterpret_cast<const float2*>(
                                 Wp + (size_t)(kk + 4) * N1);
            u64 wd0, wd1;
            PACK_F32X2(wd0, wv.x, wv.x);
            PACK_F32X2(wd1, wv.y, wv.y);
            const u64* ap = &h0P[kq * 64 + kk][0];
            ulonglong2 a01 = *reinterpret_cast<const ulonglong2*>(ap);
            ulonglong2 a23 = *reinterpret_cast<const ulonglong2*>(ap + 2);
            FMA_F32X2(acc[0], a01.x, wd0, acc[0]);
            FMA_F32X2(acc[1], a01.y, wd0, acc[1]);
            FMA_F32X2(acc[2], a23.x, wd0, acc[2]);
            FMA_F32X2(acc[3], a23.y, wd0, acc[3]);
            FMA_F32X2(acc[4], a01.x, wd1, acc[4]);
            FMA_F32X2(acc[5], a01.y, wd1, acc[5]);
            FMA_F32X2(acc[6], a23.x, wd1, acc[6]);
            FMA_F32X2(acc[7], a23.y, wd1, acc[7]);
        }
        if (kq > 0) {
            u64* dst = &pbuf[((kq - 1) * 64 + ct) * 8];
#pragma unroll
            for (int i = 0; i < 8; i += 2)
                *reinterpret_cast<ulonglong2*>(dst + i) =
                    make_ulonglong2(acc[i], acc[i + 1]);
        }
        __syncthreads();
        if (kq == 0) {
#pragma unroll
            for (int t = 0; t < 3; ++t) {
                const u64* q = &pbuf[(t * 64 + ct) * 8];
#pragma unroll
                for (int i = 0; i < 8; i += 2) {
                    ulonglong2 qq = *reinterpret_cast<const ulonglong2*>(q + i);
                    ADD_F32X2(acc[i],     acc[i],     qq.x);
                    ADD_F32X2(acc[i + 1], acc[i + 1], qq.y);
                }
            }
            float2 bv = *reinterpret_cast<const float2*>(b1 + 2 * ct);
            u64 bb0, bb1;
            PACK_F32X2(bb0, bv.x, bv.x);
            PACK_F32X2(bb1, bv.y, bv.y);
#pragma unroll
            for (int i = 0; i < 8; ++i) {
                ADD_F32X2(acc[i], acc[i], (i < 4) ? bb0 : bb1);
                float v0, v1; UNPACK_F32X2(v0, v1, acc[i]);
                PACK_F32X2(acc[i], fmaxf(v0, 0.f), fmaxf(v1, 0.f));
            }
            *reinterpret_cast<ulonglong2*>(&h1P[2 * ct][0]) =
                make_ulonglong2(acc[0], acc[1]);
            *reinterpret_cast<ulonglong2*>(&h1P[2 * ct][2]) =
                make_ulonglong2(acc[2], acc[3]);
            *reinterpret_cast<ulonglong2*>(&h1P[2 * ct + 1][0]) =
                make_ulonglong2(acc[4], acc[5]);
            *reinterpret_cast<ulonglong2*>(&h1P[2 * ct + 1][2]) =
                make_ulonglong2(acc[6], acc[7]);
        }
    }
    __syncthreads();

    // ======== Layer 2: [8,128]@[128,64]+b relu | 32 cp x 8 kq x 16 ==========
    {
        const int ct = tid & 31;
        const int kq = tid >> 5;                 // 0..7, 16 k each
        u64 acc[8];
#pragma unroll
        for (int i = 0; i < 8; ++i) acc[i] = 0ull;
        const float* Wp = W2 + (size_t)(kq * 16) * N2 + 2 * ct;

        float2 wr[4];
#pragma unroll
        for (int i = 0; i < 4; ++i)
            wr[i] = *reinterpret_cast<const float2*>(Wp + (size_t)i * N2);

#pragma unroll
        for (int kk = 0; kk < 16; ++kk) {
            float2 wv = wr[kk & 3];
            if (kk + 4 < 16)
                wr[kk & 3] = *reinterpret_cast<const float2*>(
                                 Wp + (size_t)(kk + 4) * N2);
            u64 wd0, wd1;
            PACK_F32X2(wd0, wv.x, wv.x);
            PACK_F32X2(wd1, wv.y, wv.y);
            const u64* ap = &h1P[kq * 16 + kk][0];
            ulonglong2 a01 = *reinterpret_cast<const ulonglong2*>(ap);
            ulonglong2 a23 = *reinterpret_cast<const ulonglong2*>(ap + 2);
            FMA_F32X2(acc[0], a01.x, wd0, acc[0]);
            FMA_F32X2(acc[1], a01.y, wd0, acc[1]);
            FMA_F32X2(acc[2], a23.x, wd0, acc[2]);
            FMA_F32X2(acc[3], a23.y, wd0, acc[3]);
            FMA_F32X2(acc[4], a01.x, wd1, acc[4]);
            FMA_F32X2(acc[5], a01.y, wd1, acc[5]);
            FMA_F32X2(acc[6], a23.x, wd1, acc[6]);
            FMA_F32X2(acc[7], a23.y, wd1, acc[7]);
        }
        if (kq > 0) {
            u64* dst = &pbuf[((kq - 1) * 32 + ct) * 8];
#pragma unroll
            for (int i = 0; i < 8; i += 2)
                *reinterpret_cast<ulonglong2*>(dst + i) =
                    make_ulonglong2(acc[i], acc[i + 1]);
        }
        __syncthreads();
        if (kq == 0) {
#pragma unroll
            for (int t = 0; t < 7; ++t) {
                const u64* q = &pbuf[(t * 32 + ct) * 8];
#pragma unroll
                for (int i = 0; i < 8; i += 2) {
                    ulonglong2 qq = *reinterpret_cast<const ulonglong2*>(q + i);
                    ADD_F32X2(acc[i],     acc[i],     qq.x);
                    ADD_F32X2(acc[i + 1], acc[i + 1], qq.y);
                }
            }
            float2 bv = *reinterpret_cast<const float2*>(b2 + 2 * ct);
            u64 bb0, bb1;
            PACK_F32X2(bb0, bv.x, bv.x);
            PACK_F32X2(bb1, bv.y, bv.y);
#pragma unroll
            for (int i = 0; i < 8; ++i) {
                ADD_F32X2(acc[i], acc[i], (i < 4) ? bb0 : bb1);
                float v0, v1; UNPACK_F32X2(v0, v1, acc[i]);
                const int c  = 2 * ct + (i >> 2);
                const int rp = i & 3;
                h2T[c][2 * rp    ] = fmaxf(v0, 0.f);
                h2T[c][2 * rp + 1] = fmaxf(v1, 0.f);
            }
        }
    }
    __syncthreads();

    // ======== Output: [8,64]@[64,1]+b  (8 warps = 8 rows) ===================
    {
        const int warp = tid >> 5;
        const int lane = tid & 31;
        float s = h2T[2 * lane][warp]     * Wout[2 * lane]
                + h2T[2 * lane + 1][warp] * Wout[2 * lane + 1];
#pragma unroll
        for (int o = 16; o > 0; o >>= 1)
            s += __shfl_down_sync(0xffffffffu, s, o);
        if (lane == 0)
            out[p0 + warp] = s + bout[0];
    }
}

// d_in order (metadata): [0] batch_num_nodes (unused), [1] features,
// [2] W0, [3] b0, [4] W1, [5] b1, [6] W2, [7] b2, [8] Wout, [9] bout.
extern "C" void kernel_launch(void* const* d_in, const int* in_sizes, int n_in,
                              void* d_out, int out_size)
{
    const float* features = (const float*)d_in[1];
    const float* W0   = (const float*)d_in[2];
    const float* b0   = (const float*)d_in[3];
    const float* W1   = (const float*)d_in[4];
    const float* b1   = (const float*)d_in[5];
    const float* W2   = (const float*)d_in[6];
    const float* b2   = (const float*)d_in[7];
    const float* Wout = (const float*)d_in[8];
    const float* bout = (const float*)d_in[9];
    float* out = (float*)d_out;

    seg_sum_kernel<<<B_PAIRS, THREADS>>>(features);
    mlp_kernel<<<B_PAIRS / RTILE, THREADS>>>(W0, b0, W1, b1, W2, b2,
                                             Wout, bout, out);
}